// round 3
// baseline (speedup 1.0000x reference)
#include <cuda_runtime.h>
#include <cuda_fp16.h>
#include <cstdint>

// ============================================================================
// Problem dims (fixed by the dataset)
// ============================================================================
#define BB 4
#define TT 256
#define UU 128
#define EE 512
#define DD 640
#define JJ 640
#define VV 1024

// ============================================================================
// Scratch (__device__ globals — allocation-free)
// ============================================================================
__device__ float g_enc_proj[BB * TT * JJ];   // (1024, 640) fp32
__device__ float g_dec_proj[BB * UU * JJ];   // (512, 640)  fp32
__device__ __half g_wt[VV * JJ];             // W_joint^T (1024, 640) fp16

// ============================================================================
// Stage 1a: fp32 projection GEMM  C[M,N] = A[M,K] * W[K,N] + bias  (small)
// ============================================================================
__global__ void proj_gemm_kernel(const float* __restrict__ A,
                                 const float* __restrict__ W,
                                 const float* __restrict__ bias,
                                 float* __restrict__ C,
                                 int M, int N, int K) {
    __shared__ float As[64][16];
    __shared__ float Ws[16][64];
    const int tid = threadIdx.x;
    const int tx = tid % 16, ty = tid / 16;
    const int m0 = blockIdx.y * 64, n0 = blockIdx.x * 64;

    float acc[4][4] = {};

    for (int k0 = 0; k0 < K; k0 += 16) {
        {
            int r = tid / 4, c = (tid % 4) * 4;
            float4 a4 = *(const float4*)&A[(size_t)(m0 + r) * K + k0 + c];
            *(float4*)&As[r][c] = a4;
            int rw = tid / 16, cw = (tid % 16) * 4;
            float4 w4 = *(const float4*)&W[(size_t)(k0 + rw) * N + n0 + cw];
            *(float4*)&Ws[rw][cw] = w4;
        }
        __syncthreads();
#pragma unroll
        for (int k = 0; k < 16; k++) {
            float a[4], w[4];
#pragma unroll
            for (int i = 0; i < 4; i++) a[i] = As[ty * 4 + i][k];
#pragma unroll
            for (int j = 0; j < 4; j++) w[j] = Ws[k][tx * 4 + j];
#pragma unroll
            for (int i = 0; i < 4; i++)
#pragma unroll
                for (int j = 0; j < 4; j++) acc[i][j] = fmaf(a[i], w[j], acc[i][j]);
        }
        __syncthreads();
    }
#pragma unroll
    for (int i = 0; i < 4; i++) {
#pragma unroll
        for (int j = 0; j < 4; j++) {
            int gm = m0 + ty * 4 + i, gn = n0 + tx * 4 + j;
            C[(size_t)gm * N + gn] = acc[i][j] + bias[gn];
        }
    }
}

// ============================================================================
// Stage 1b: transpose W_joint (J,V) fp32 -> Wt (V,J) fp16
// ============================================================================
__global__ void transpose_fp16_kernel(const float* __restrict__ Wj) {
    __shared__ float tile[32][33];
    const int v0 = blockIdx.x * 32, j0 = blockIdx.y * 32;
    const int tx = threadIdx.x, ty = threadIdx.y;  // (32, 8)
#pragma unroll
    for (int i = 0; i < 4; i++) {
        int j = j0 + ty + i * 8;
        tile[ty + i * 8][tx] = Wj[(size_t)j * VV + v0 + tx];
    }
    __syncthreads();
#pragma unroll
    for (int i = 0; i < 4; i++) {
        int v = v0 + ty + i * 8;
        int j = j0 + tx;
        g_wt[(size_t)v * JJ + j] = __float2half_rn(tile[tx][ty + i * 8]);
    }
}

// ============================================================================
// Stage 2: fused tanh-joint + vocab GEMM via mma.sync (fp16 in, fp32 acc)
//
// Grid (4, 1024): CTA = one (b,t) x 256 vocab cols. M=128 (u), N=256, K=J=640
// in 64-wide chunks. A tile (tanh joint) generated in SMEM each chunk.
// 512 threads = 16 warps in 4(M) x 4(N); warp tile 32 x 64.
// ============================================================================
#define KC 64
#define NCHUNK (JJ / KC)                  // 10
#define SM_A_BYTES (128 * KC * 2)         // 16 KB
#define SM_B_BYTES (256 * KC * 2)         // 32 KB
#define SM_TOTAL (SM_A_BYTES + SM_B_BYTES)

__device__ __forceinline__ uint32_t smem_u32(const void* p) {
    uint32_t r;
    asm("{ .reg .u64 t; cvta.to.shared.u64 t, %1; cvt.u32.u64 %0, t; }"
        : "=r"(r) : "l"(p));
    return r;
}

// rows are 128B wide; XOR bits[6:4] with row[2:0] for conflict-free ldmatrix
__device__ __forceinline__ uint32_t swz(uint32_t byte_off) {
    return byte_off ^ ((byte_off >> 3) & 0x70u);
}

__device__ __forceinline__ float tanh_fast(float x) {
    float xc = fminf(fmaxf(x, -15.0f), 15.0f);
    float e = __expf(2.0f * xc);
    return __fdividef(e - 1.0f, e + 1.0f);
}

__device__ __forceinline__ void ldsm_x4(uint32_t addr, uint32_t& r0, uint32_t& r1,
                                        uint32_t& r2, uint32_t& r3) {
    asm volatile("ldmatrix.sync.aligned.m8n8.x4.shared.b16 {%0,%1,%2,%3}, [%4];"
                 : "=r"(r0), "=r"(r1), "=r"(r2), "=r"(r3) : "r"(addr));
}

__device__ __forceinline__ void mma16816(float* c, const uint32_t* a,
                                         const uint32_t* b) {
    asm volatile(
        "mma.sync.aligned.m16n8k16.row.col.f32.f16.f16.f32 "
        "{%0,%1,%2,%3}, {%4,%5,%6,%7}, {%8,%9}, {%0,%1,%2,%3};"
        : "+f"(c[0]), "+f"(c[1]), "+f"(c[2]), "+f"(c[3])
        : "r"(a[0]), "r"(a[1]), "r"(a[2]), "r"(a[3]), "r"(b[0]), "r"(b[1]));
}

__global__ void __launch_bounds__(512)
joint_vocab_kernel(const float* __restrict__ b_joint, float* __restrict__ out) {
    extern __shared__ __align__(128) char smem[];
    char* sA = smem;                 // 128 x 64 fp16, swizzled
    char* sB = smem + SM_A_BYTES;    // 256 x 64 fp16, swizzled
    const uint32_t sAu = smem_u32(sA);
    const uint32_t sBu = smem_u32(sB);

    const int tid = threadIdx.x;
    const int lane = tid & 31;
    const int wid = tid >> 5;
    const int warp_m = wid & 3;      // 0..3 -> m0 = warp_m*32
    const int warp_n = wid >> 2;     // 0..3 -> n0 = warp_n*64

    const int nt = blockIdx.x;       // vocab tile 0..3
    const int bt = blockIdx.y;       // b*T + t
    const int b  = bt >> 8;          // T = 256
    const int v0 = nt * 256;

    const float* encrow = g_enc_proj + (size_t)bt * JJ;
    const float* decb   = g_dec_proj + (size_t)b * UU * JJ;

    // A-gen mapping: thread -> (j pair, u stripe)
    const int jp = tid & 31;         // j pair index: j = j0 + 2*jp
    const int ug = tid >> 5;         // u base 0..15; u = ug + i*16

    // B-load mapping: idx -> (n row, 16B group)
    // idx = tid + r*512; n = idx>>3 (0..255), g = idx&7 (8 fp16 = 16B)

    float acc[2][8][4];
#pragma unroll
    for (int mi = 0; mi < 2; mi++)
#pragma unroll
        for (int ni = 0; ni < 8; ni++)
#pragma unroll
            for (int c = 0; c < 4; c++) acc[mi][ni][c] = 0.0f;

    // precomputed ldmatrix smem addresses (advance by k inside loop)
    // A: row = warp_m*32 + mi*16 + (lane & 15); col byte = (k0 + (lane>>4)*8)*2
    const int a_row = warp_m * 32 + (lane & 15);
    const int a_kb  = (lane >> 4) * 16;            // byte offset within k
    // B: n = warp_n*64 + nq*16 + (lane>>4)*8 + (lane&7); k byte = (k0 + ((lane>>3)&1)*8)*2
    const int b_nrow = warp_n * 64 + ((lane >> 4) << 3) + (lane & 7);
    const int b_kb   = ((lane >> 3) & 1) * 16;

    for (int kc = 0; kc < NCHUNK; kc++) {
        const int j0 = kc * KC;

        __syncthreads();  // previous chunk's ldmatrix reads done before overwrite

        // ---- issue B global loads first (L2 latency hidden behind tanh) ----
        uint4 bld[4];
#pragma unroll
        for (int r = 0; r < 4; r++) {
            int idx = tid + r * 512;
            int n = idx >> 3, g = idx & 7;
            bld[r] = *(const uint4*)(g_wt + (size_t)(v0 + n) * JJ + j0 + g * 8);
        }

        // ---- A tile: tanh(enc + dec) -> fp16, swizzled ----
        {
            float2 e2 = *(const float2*)(encrow + j0 + 2 * jp);
#pragma unroll
            for (int i = 0; i < 8; i++) {
                int u = ug + i * 16;
                float2 d2 = *(const float2*)(decb + (size_t)u * JJ + j0 + 2 * jp);
                float x0 = tanh_fast(e2.x + d2.x);
                float x1 = tanh_fast(e2.y + d2.y);
                __half2 h2 = __floats2half2_rn(x0, x1);
                uint32_t off = swz((uint32_t)(u * 128 + jp * 4));
                *(uint32_t*)(sA + off) = *(uint32_t*)&h2;
            }
        }

        // ---- store B tile, swizzled ----
#pragma unroll
        for (int r = 0; r < 4; r++) {
            int idx = tid + r * 512;
            int n = idx >> 3, g = idx & 7;
            uint32_t off = swz((uint32_t)(n * 128 + g * 16));
            *(uint4*)(sB + off) = bld[r];
        }

        __syncthreads();

        // ---- 4 x k16 MMA steps ----
#pragma unroll
        for (int ks = 0; ks < 4; ks++) {
            const int k0b = ks * 32;  // 16 fp16 = 32 bytes
            uint32_t a[2][4];
#pragma unroll
            for (int mi = 0; mi < 2; mi++) {
                uint32_t addr = sAu +
                    swz((uint32_t)((a_row + mi * 16) * 128 + k0b + a_kb));
                ldsm_x4(addr, a[mi][0], a[mi][1], a[mi][2], a[mi][3]);
            }
            uint32_t bf[8][2];
#pragma unroll
            for (int nq = 0; nq < 4; nq++) {
                uint32_t addr = sBu +
                    swz((uint32_t)((b_nrow + nq * 16) * 128 + k0b + b_kb));
                ldsm_x4(addr, bf[nq * 2][0], bf[nq * 2][1],
                        bf[nq * 2 + 1][0], bf[nq * 2 + 1][1]);
            }
#pragma unroll
            for (int mi = 0; mi < 2; mi++)
#pragma unroll
                for (int ni = 0; ni < 8; ni++)
                    mma16816(acc[mi][ni], a[mi], bf[ni]);
        }
    }

    // ---- Epilogue: +bias, write fp32 ----
    {
        const int rowb = warp_m * 32 + (lane >> 2);
        const int colb = warp_n * 64 + (lane & 3) * 2;
        float* outbt = out + ((size_t)bt * UU) * VV + v0;
        const float* bp = b_joint + v0;
#pragma unroll
        for (int ni = 0; ni < 8; ni++) {
            int c_ = colb + ni * 8;
            float2 b2 = *(const float2*)(bp + c_);
#pragma unroll
            for (int mi = 0; mi < 2; mi++) {
                int r_ = rowb + mi * 16;
                float2 o0 = { acc[mi][ni][0] + b2.x, acc[mi][ni][1] + b2.y };
                float2 o1 = { acc[mi][ni][2] + b2.x, acc[mi][ni][3] + b2.y };
                *(float2*)(outbt + (size_t)r_ * VV + c_) = o0;
                *(float2*)(outbt + (size_t)(r_ + 8) * VV + c_) = o1;
            }
        }
    }
}

// ============================================================================
// Launch
// ============================================================================
extern "C" void kernel_launch(void* const* d_in, const int* in_sizes, int n_in,
                              void* d_out, int out_size) {
    const float* enc     = (const float*)d_in[0];
    const float* dec     = (const float*)d_in[1];
    const float* W_enc   = (const float*)d_in[2];
    const float* b_enc   = (const float*)d_in[3];
    const float* W_dec   = (const float*)d_in[4];
    const float* b_dec   = (const float*)d_in[5];
    const float* W_joint = (const float*)d_in[6];
    const float* b_joint = (const float*)d_in[7];
    float* out = (float*)d_out;

    void *p_encp = nullptr, *p_decp = nullptr;
    cudaGetSymbolAddress(&p_encp, g_enc_proj);
    cudaGetSymbolAddress(&p_decp, g_dec_proj);

    // enc_proj: (1024, 512) x (512, 640)
    proj_gemm_kernel<<<dim3(JJ / 64, (BB * TT) / 64), 256>>>(
        enc, W_enc, b_enc, (float*)p_encp, BB * TT, JJ, EE);
    // dec_proj: (512, 640) x (640, 640)
    proj_gemm_kernel<<<dim3(JJ / 64, (BB * UU) / 64), 256>>>(
        dec, W_dec, b_dec, (float*)p_decp, BB * UU, JJ, DD);
    // W_joint transpose -> fp16
    transpose_fp16_kernel<<<dim3(VV / 32, JJ / 32), dim3(32, 8)>>>(W_joint);

    // fused joint + vocab GEMM
    cudaFuncSetAttribute(joint_vocab_kernel,
                         cudaFuncAttributeMaxDynamicSharedMemorySize, SM_TOTAL);
    joint_vocab_kernel<<<dim3(VV / 256, BB * TT), 512, SM_TOTAL>>>(b_joint, out);
}

// round 4
// speedup vs baseline: 1.3608x; 1.3608x over previous
#include <cuda_runtime.h>
#include <cuda_fp16.h>
#include <cstdint>

// ============================================================================
// Problem dims (fixed by the dataset)
// ============================================================================
#define BB 4
#define TT 256
#define UU 128
#define EE 512
#define DD 640
#define JJ 640
#define VV 1024

// ============================================================================
// Scratch (__device__ globals — allocation-free)
// ============================================================================
__device__ float g_enc_proj[BB * TT * JJ];   // (1024, 640) fp32
__device__ float g_dec_proj[BB * UU * JJ];   // (512, 640)  fp32
__device__ __half g_wt[VV * JJ];             // W_joint^T (1024, 640) fp16

// ============================================================================
// Stage 1a: fp32 projection GEMM  C[M,N] = A[M,K] * W[K,N] + bias  (small)
// ============================================================================
__global__ void proj_gemm_kernel(const float* __restrict__ A,
                                 const float* __restrict__ W,
                                 const float* __restrict__ bias,
                                 float* __restrict__ C,
                                 int M, int N, int K) {
    __shared__ float As[64][16];
    __shared__ float Ws[16][64];
    const int tid = threadIdx.x;
    const int tx = tid % 16, ty = tid / 16;
    const int m0 = blockIdx.y * 64, n0 = blockIdx.x * 64;

    float acc[4][4] = {};

    for (int k0 = 0; k0 < K; k0 += 16) {
        {
            int r = tid / 4, c = (tid % 4) * 4;
            float4 a4 = *(const float4*)&A[(size_t)(m0 + r) * K + k0 + c];
            *(float4*)&As[r][c] = a4;
            int rw = tid / 16, cw = (tid % 16) * 4;
            float4 w4 = *(const float4*)&W[(size_t)(k0 + rw) * N + n0 + cw];
            *(float4*)&Ws[rw][cw] = w4;
        }
        __syncthreads();
#pragma unroll
        for (int k = 0; k < 16; k++) {
            float a[4], w[4];
#pragma unroll
            for (int i = 0; i < 4; i++) a[i] = As[ty * 4 + i][k];
#pragma unroll
            for (int j = 0; j < 4; j++) w[j] = Ws[k][tx * 4 + j];
#pragma unroll
            for (int i = 0; i < 4; i++)
#pragma unroll
                for (int j = 0; j < 4; j++) acc[i][j] = fmaf(a[i], w[j], acc[i][j]);
        }
        __syncthreads();
    }
#pragma unroll
    for (int i = 0; i < 4; i++) {
#pragma unroll
        for (int j = 0; j < 4; j++) {
            int gm = m0 + ty * 4 + i, gn = n0 + tx * 4 + j;
            C[(size_t)gm * N + gn] = acc[i][j] + bias[gn];
        }
    }
}

// ============================================================================
// Stage 1b: transpose W_joint (J,V) fp32 -> Wt (V,J) fp16
// ============================================================================
__global__ void transpose_fp16_kernel(const float* __restrict__ Wj) {
    __shared__ float tile[32][33];
    const int v0 = blockIdx.x * 32, j0 = blockIdx.y * 32;
    const int tx = threadIdx.x, ty = threadIdx.y;  // (32, 8)
#pragma unroll
    for (int i = 0; i < 4; i++) {
        int j = j0 + ty + i * 8;
        tile[ty + i * 8][tx] = Wj[(size_t)j * VV + v0 + tx];
    }
    __syncthreads();
#pragma unroll
    for (int i = 0; i < 4; i++) {
        int v = v0 + ty + i * 8;
        int j = j0 + tx;
        g_wt[(size_t)v * JJ + j] = __float2half_rn(tile[tx][ty + i * 8]);
    }
}

// ============================================================================
// Stage 2: fused tanh-joint + vocab GEMM via mma.sync (fp16 in, fp32 acc)
//
// Grid (4, 1024): CTA = one (b,t) x 256 vocab cols. M=128 (u), N=256, K=J=640
// in 64-wide chunks. A tile (tanh joint) generated in SMEM per chunk.
// DOUBLE-BUFFERED: cp.async B + dec LDGs for chunk k+1 issued BEFORE the MMA
// of chunk k; tanh+STS consume them after, hidden under the tensor drain.
// 512 threads = 16 warps in 4(M) x 4(N); warp tile 32 x 64.
// ============================================================================
#define KC 64
#define NCHUNK (JJ / KC)                  // 10
#define STAGE_BYTES (128 * KC * 2 + 256 * KC * 2)   // 16KB A + 32KB B = 48KB
#define SM_TOTAL (2 * STAGE_BYTES)                   // 96KB

__device__ __forceinline__ uint32_t smem_u32(const void* p) {
    uint32_t r;
    asm("{ .reg .u64 t; cvta.to.shared.u64 t, %1; cvt.u32.u64 %0, t; }"
        : "=r"(r) : "l"(p));
    return r;
}

// rows are 128B wide; XOR bits[6:4] with row[2:0] for conflict-free ldmatrix
__device__ __forceinline__ uint32_t swz(uint32_t byte_off) {
    return byte_off ^ ((byte_off >> 3) & 0x70u);
}

__device__ __forceinline__ float tanh_approx(float x) {
    float y;
    asm("tanh.approx.f32 %0, %1;" : "=f"(y) : "f"(x));
    return y;
}

__device__ __forceinline__ void cp_async16(uint32_t dst, const void* src) {
    asm volatile("cp.async.cg.shared.global [%0], [%1], 16;"
                 :: "r"(dst), "l"(src));
}
#define CP_COMMIT() asm volatile("cp.async.commit_group;")
#define CP_WAIT0()  asm volatile("cp.async.wait_group 0;")

__device__ __forceinline__ void ldsm_x4(uint32_t addr, uint32_t& r0, uint32_t& r1,
                                        uint32_t& r2, uint32_t& r3) {
    asm volatile("ldmatrix.sync.aligned.m8n8.x4.shared.b16 {%0,%1,%2,%3}, [%4];"
                 : "=r"(r0), "=r"(r1), "=r"(r2), "=r"(r3) : "r"(addr));
}

__device__ __forceinline__ void mma16816(float* c, const uint32_t* a,
                                         const uint32_t* b) {
    asm volatile(
        "mma.sync.aligned.m16n8k16.row.col.f32.f16.f16.f32 "
        "{%0,%1,%2,%3}, {%4,%5,%6,%7}, {%8,%9}, {%0,%1,%2,%3};"
        : "+f"(c[0]), "+f"(c[1]), "+f"(c[2]), "+f"(c[3])
        : "r"(a[0]), "r"(a[1]), "r"(a[2]), "r"(a[3]), "r"(b[0]), "r"(b[1]));
}

__global__ void __launch_bounds__(512, 1)
joint_vocab_kernel(const float* __restrict__ b_joint, float* __restrict__ out) {
    extern __shared__ __align__(128) char smem[];
    const uint32_t s0 = smem_u32(smem);
    // stage s: A at s*STAGE_BYTES, B at s*STAGE_BYTES + 16KB

    const int tid = threadIdx.x;
    const int lane = tid & 31;
    const int wid = tid >> 5;
    const int warp_m = wid & 3;      // m0 = warp_m*32
    const int warp_n = wid >> 2;     // n0 = warp_n*64

    const int nt = blockIdx.x;       // vocab tile 0..3
    const int bt = blockIdx.y;       // b*T + t
    const int b  = bt >> 8;          // T = 256
    const int v0 = nt * 256;

    const float* encrow = g_enc_proj + (size_t)bt * JJ;
    const float* decb   = g_dec_proj + (size_t)b * UU * JJ;

    // A-gen mapping: j = j0 + 2*jp; u = ug + i*16
    const int jp = tid & 31;
    const int ug = tid >> 5;
    // B cp.async mapping: idx = tid + r*512; n = idx>>3, g = idx&7 (16B)

    // ldmatrix fragment addressing (within a stage)
    const int a_row = warp_m * 32 + (lane & 15);
    const int a_kb  = (lane >> 4) * 16;
    const int b_nrow = warp_n * 64 + ((lane >> 4) << 3) + (lane & 7);
    const int b_kb   = ((lane >> 3) & 1) * 16;

    float acc[2][8][4];
#pragma unroll
    for (int mi = 0; mi < 2; mi++)
#pragma unroll
        for (int ni = 0; ni < 8; ni++)
#pragma unroll
            for (int c = 0; c < 4; c++) acc[mi][ni][c] = 0.0f;

    // ---- prologue: generate stage 0 ----
    {
        const int j0 = 0;
        const uint32_t sB = s0 + 16384;
#pragma unroll
        for (int r = 0; r < 4; r++) {
            int idx = tid + r * 512;
            int n = idx >> 3, g = idx & 7;
            cp_async16(sB + swz((uint32_t)(n * 128 + g * 16)),
                       g_wt + (size_t)(v0 + n) * JJ + j0 + g * 8);
        }
        CP_COMMIT();
        float2 e2 = *(const float2*)(encrow + j0 + 2 * jp);
        float2 d2[8];
#pragma unroll
        for (int i = 0; i < 8; i++)
            d2[i] = *(const float2*)(decb + (size_t)(ug + i * 16) * JJ + j0 + 2 * jp);
#pragma unroll
        for (int i = 0; i < 8; i++) {
            int u = ug + i * 16;
            float x0 = tanh_approx(e2.x + d2[i].x);
            float x1 = tanh_approx(e2.y + d2[i].y);
            __half2 h2 = __floats2half2_rn(x0, x1);
            *(uint32_t*)(smem + swz((uint32_t)(u * 128 + jp * 4))) = *(uint32_t*)&h2;
        }
        CP_WAIT0();
        __syncthreads();
    }

    // ---- main pipeline ----
    for (int kc = 0; kc < NCHUNK; kc++) {
        const uint32_t cur = (uint32_t)(kc & 1) * STAGE_BYTES;
        const uint32_t nxt = (uint32_t)((kc + 1) & 1) * STAGE_BYTES;
        const bool has_next = (kc + 1) < NCHUNK;
        const int j0n = (kc + 1) * KC;

        // -- issue next-chunk loads first (in flight during MMA) --
        float2 e2, d2[8];
        if (has_next) {
            const uint32_t sBn = s0 + nxt + 16384;
#pragma unroll
            for (int r = 0; r < 4; r++) {
                int idx = tid + r * 512;
                int n = idx >> 3, g = idx & 7;
                cp_async16(sBn + swz((uint32_t)(n * 128 + g * 16)),
                           g_wt + (size_t)(v0 + n) * JJ + j0n + g * 8);
            }
            CP_COMMIT();
            e2 = *(const float2*)(encrow + j0n + 2 * jp);
#pragma unroll
            for (int i = 0; i < 8; i++)
                d2[i] = *(const float2*)(decb + (size_t)(ug + i * 16) * JJ + j0n + 2 * jp);
        }

        // -- MMA on current stage --
        const uint32_t sAc = s0 + cur;
        const uint32_t sBc = s0 + cur + 16384;
#pragma unroll
        for (int ks = 0; ks < 4; ks++) {
            const int k0b = ks * 32;
            uint32_t a[2][4];
#pragma unroll
            for (int mi = 0; mi < 2; mi++) {
                uint32_t addr = sAc +
                    swz((uint32_t)((a_row + mi * 16) * 128 + k0b + a_kb));
                ldsm_x4(addr, a[mi][0], a[mi][1], a[mi][2], a[mi][3]);
            }
            uint32_t bf[8][2];
#pragma unroll
            for (int nq = 0; nq < 4; nq++) {
                uint32_t addr = sBc +
                    swz((uint32_t)((b_nrow + nq * 16) * 128 + k0b + b_kb));
                ldsm_x4(addr, bf[nq * 2][0], bf[nq * 2][1],
                        bf[nq * 2 + 1][0], bf[nq * 2 + 1][1]);
            }
#pragma unroll
            for (int mi = 0; mi < 2; mi++)
#pragma unroll
                for (int ni = 0; ni < 8; ni++)
                    mma16816(acc[mi][ni], a[mi], bf[ni]);
        }

        // -- consume next-chunk loads: tanh -> STS (under tensor drain) --
        if (has_next) {
            char* sAn = smem + nxt;
#pragma unroll
            for (int i = 0; i < 8; i++) {
                int u = ug + i * 16;
                float x0 = tanh_approx(e2.x + d2[i].x);
                float x1 = tanh_approx(e2.y + d2[i].y);
                __half2 h2 = __floats2half2_rn(x0, x1);
                *(uint32_t*)(sAn + swz((uint32_t)(u * 128 + jp * 4))) = *(uint32_t*)&h2;
            }
            CP_WAIT0();
        }
        __syncthreads();
    }

    // ---- Epilogue: +bias, write fp32 ----
    {
        const int rowb = warp_m * 32 + (lane >> 2);
        const int colb = warp_n * 64 + (lane & 3) * 2;
        float* outbt = out + ((size_t)bt * UU) * VV + v0;
        const float* bp = b_joint + v0;
#pragma unroll
        for (int ni = 0; ni < 8; ni++) {
            int c_ = colb + ni * 8;
            float2 b2 = *(const float2*)(bp + c_);
#pragma unroll
            for (int mi = 0; mi < 2; mi++) {
                int r_ = rowb + mi * 16;
                float2 o0 = { acc[mi][ni][0] + b2.x, acc[mi][ni][1] + b2.y };
                float2 o1 = { acc[mi][ni][2] + b2.x, acc[mi][ni][3] + b2.y };
                *(float2*)(outbt + (size_t)r_ * VV + c_) = o0;
                *(float2*)(outbt + (size_t)(r_ + 8) * VV + c_) = o1;
            }
        }
    }
}

// ============================================================================
// Launch
// ============================================================================
extern "C" void kernel_launch(void* const* d_in, const int* in_sizes, int n_in,
                              void* d_out, int out_size) {
    const float* enc     = (const float*)d_in[0];
    const float* dec     = (const float*)d_in[1];
    const float* W_enc   = (const float*)d_in[2];
    const float* b_enc   = (const float*)d_in[3];
    const float* W_dec   = (const float*)d_in[4];
    const float* b_dec   = (const float*)d_in[5];
    const float* W_joint = (const float*)d_in[6];
    const float* b_joint = (const float*)d_in[7];
    float* out = (float*)d_out;

    void *p_encp = nullptr, *p_decp = nullptr;
    cudaGetSymbolAddress(&p_encp, g_enc_proj);
    cudaGetSymbolAddress(&p_decp, g_dec_proj);

    // enc_proj: (1024, 512) x (512, 640)
    proj_gemm_kernel<<<dim3(JJ / 64, (BB * TT) / 64), 256>>>(
        enc, W_enc, b_enc, (float*)p_encp, BB * TT, JJ, EE);
    // dec_proj: (512, 640) x (640, 640)
    proj_gemm_kernel<<<dim3(JJ / 64, (BB * UU) / 64), 256>>>(
        dec, W_dec, b_dec, (float*)p_decp, BB * UU, JJ, DD);
    // W_joint transpose -> fp16
    transpose_fp16_kernel<<<dim3(VV / 32, JJ / 32), dim3(32, 8)>>>(W_joint);

    // fused joint + vocab GEMM
    cudaFuncSetAttribute(joint_vocab_kernel,
                         cudaFuncAttributeMaxDynamicSharedMemorySize, SM_TOTAL);
    joint_vocab_kernel<<<dim3(VV / 256, BB * TT), 512, SM_TOTAL>>>(b_joint, out);
}

// round 5
// speedup vs baseline: 1.4363x; 1.0555x over previous
#include <cuda_runtime.h>
#include <cuda_fp16.h>
#include <cstdint>

// ============================================================================
// Problem dims (fixed by the dataset)
// ============================================================================
#define BB 4
#define TT 256
#define UU 128
#define EE 512
#define DD 640
#define JJ 640
#define VV 1024

// ============================================================================
// Scratch (__device__ globals — allocation-free)
// ============================================================================
__device__ float g_enc_proj[BB * TT * JJ];   // (1024, 640) fp32
__device__ float g_dec_proj[BB * UU * JJ];   // (512, 640)  fp32
__device__ __half g_wt[VV * JJ];             // W_joint^T (1024, 640) fp16

// ============================================================================
// Stage 1a: fp32 projection GEMM  C[M,N] = A[M,K] * W[K,N] + bias  (small)
// ============================================================================
__global__ void proj_gemm_kernel(const float* __restrict__ A,
                                 const float* __restrict__ W,
                                 const float* __restrict__ bias,
                                 float* __restrict__ C,
                                 int M, int N, int K) {
    __shared__ float As[64][16];
    __shared__ float Ws[16][64];
    const int tid = threadIdx.x;
    const int tx = tid % 16, ty = tid / 16;
    const int m0 = blockIdx.y * 64, n0 = blockIdx.x * 64;

    float acc[4][4] = {};

    for (int k0 = 0; k0 < K; k0 += 16) {
        {
            int r = tid / 4, c = (tid % 4) * 4;
            float4 a4 = *(const float4*)&A[(size_t)(m0 + r) * K + k0 + c];
            *(float4*)&As[r][c] = a4;
            int rw = tid / 16, cw = (tid % 16) * 4;
            float4 w4 = *(const float4*)&W[(size_t)(k0 + rw) * N + n0 + cw];
            *(float4*)&Ws[rw][cw] = w4;
        }
        __syncthreads();
#pragma unroll
        for (int k = 0; k < 16; k++) {
            float a[4], w[4];
#pragma unroll
            for (int i = 0; i < 4; i++) a[i] = As[ty * 4 + i][k];
#pragma unroll
            for (int j = 0; j < 4; j++) w[j] = Ws[k][tx * 4 + j];
#pragma unroll
            for (int i = 0; i < 4; i++)
#pragma unroll
                for (int j = 0; j < 4; j++) acc[i][j] = fmaf(a[i], w[j], acc[i][j]);
        }
        __syncthreads();
    }
#pragma unroll
    for (int i = 0; i < 4; i++) {
#pragma unroll
        for (int j = 0; j < 4; j++) {
            int gm = m0 + ty * 4 + i, gn = n0 + tx * 4 + j;
            C[(size_t)gm * N + gn] = acc[i][j] + bias[gn];
        }
    }
}

// ============================================================================
// Stage 1b: transpose W_joint (J,V) fp32 -> Wt (V,J) fp16
// ============================================================================
__global__ void transpose_fp16_kernel(const float* __restrict__ Wj) {
    __shared__ float tile[32][33];
    const int v0 = blockIdx.x * 32, j0 = blockIdx.y * 32;
    const int tx = threadIdx.x, ty = threadIdx.y;  // (32, 8)
#pragma unroll
    for (int i = 0; i < 4; i++) {
        int j = j0 + ty + i * 8;
        tile[ty + i * 8][tx] = Wj[(size_t)j * VV + v0 + tx];
    }
    __syncthreads();
#pragma unroll
    for (int i = 0; i < 4; i++) {
        int v = v0 + ty + i * 8;
        int j = j0 + tx;
        g_wt[(size_t)v * JJ + j] = __float2half_rn(tile[tx][ty + i * 8]);
    }
}

// ============================================================================
// Stage 2: fused tanh-joint + vocab GEMM via mma.sync (fp16 in, fp32 acc)
//
// Grid (8, 1024): blockIdx.x = (mt<<2)|nt. CTA = 64 u-rows x 256 vocab cols.
// 256 threads = 8 warps (2 M x 4 N), warp tile 32x64. K = J = 640 in 64-chunks.
// Double-buffered; 2 CTAs co-resident per SM so gen/barrier phases of one CTA
// hide under the MMA phase of the other.
// ============================================================================
#define KC 64
#define NCHUNK (JJ / KC)                        // 10
#define MT 64                                   // M rows per CTA
#define SM_A_BYTES (MT * KC * 2)                // 8 KB
#define SM_B_BYTES (256 * KC * 2)               // 32 KB
#define STAGE_BYTES (SM_A_BYTES + SM_B_BYTES)   // 40 KB
#define SM_TOTAL (2 * STAGE_BYTES)              // 80 KB (x2 CTAs = 160 KB/SM)

__device__ __forceinline__ uint32_t smem_u32(const void* p) {
    uint32_t r;
    asm("{ .reg .u64 t; cvta.to.shared.u64 t, %1; cvt.u32.u64 %0, t; }"
        : "=r"(r) : "l"(p));
    return r;
}

// rows are 128B wide; XOR bits[6:4] with row[2:0] for conflict-free ldmatrix
__device__ __forceinline__ uint32_t swz(uint32_t byte_off) {
    return byte_off ^ ((byte_off >> 3) & 0x70u);
}

__device__ __forceinline__ float tanh_approx(float x) {
    float y;
    asm("tanh.approx.f32 %0, %1;" : "=f"(y) : "f"(x));
    return y;
}

__device__ __forceinline__ void cp_async16(uint32_t dst, const void* src) {
    asm volatile("cp.async.cg.shared.global [%0], [%1], 16;"
                 :: "r"(dst), "l"(src));
}
#define CP_COMMIT() asm volatile("cp.async.commit_group;")
#define CP_WAIT0()  asm volatile("cp.async.wait_group 0;")

__device__ __forceinline__ void ldsm_x4(uint32_t addr, uint32_t& r0, uint32_t& r1,
                                        uint32_t& r2, uint32_t& r3) {
    asm volatile("ldmatrix.sync.aligned.m8n8.x4.shared.b16 {%0,%1,%2,%3}, [%4];"
                 : "=r"(r0), "=r"(r1), "=r"(r2), "=r"(r3) : "r"(addr));
}

__device__ __forceinline__ void mma16816(float* c, const uint32_t* a,
                                         const uint32_t* b) {
    asm volatile(
        "mma.sync.aligned.m16n8k16.row.col.f32.f16.f16.f32 "
        "{%0,%1,%2,%3}, {%4,%5,%6,%7}, {%8,%9}, {%0,%1,%2,%3};"
        : "+f"(c[0]), "+f"(c[1]), "+f"(c[2]), "+f"(c[3])
        : "r"(a[0]), "r"(a[1]), "r"(a[2]), "r"(a[3]), "r"(b[0]), "r"(b[1]));
}

__global__ void __launch_bounds__(256, 2)
joint_vocab_kernel(const float* __restrict__ b_joint, float* __restrict__ out) {
    extern __shared__ __align__(128) char smem[];
    const uint32_t s0 = smem_u32(smem);
    // stage s: A at s*STAGE_BYTES, B at s*STAGE_BYTES + SM_A_BYTES

    const int tid = threadIdx.x;
    const int lane = tid & 31;
    const int wid = tid >> 5;            // 0..7
    const int warp_m = wid & 1;          // m0 = warp_m*32
    const int warp_n = wid >> 1;         // 0..3 -> n0 = warp_n*64

    const int bx = blockIdx.x;           // 0..7
    const int v0 = (bx & 3) * 256;       // vocab tile
    const int u0 = (bx >> 2) * MT;       // u half
    const int bt = blockIdx.y;           // b*T + t
    const int b  = bt >> 8;              // T = 256

    const float* encrow = g_enc_proj + (size_t)bt * JJ;
    const float* decb   = g_dec_proj + ((size_t)b * UU + u0) * JJ;

    // A-gen mapping: j = j0 + 2*jp; u = ug + i*8  (64 rows, 8 iters)
    const int jp = tid & 31;
    const int ug = tid >> 5;
    // B cp.async mapping: idx = tid + r*256 (r<8); n = idx>>3, g = idx&7 (16B)

    // ldmatrix fragment addressing (within a stage)
    const int a_row = warp_m * 32 + (lane & 15);
    const int a_kb  = (lane >> 4) * 16;
    const int b_nrow = warp_n * 64 + ((lane >> 4) << 3) + (lane & 7);
    const int b_kb   = ((lane >> 3) & 1) * 16;

    float acc[2][8][4];
#pragma unroll
    for (int mi = 0; mi < 2; mi++)
#pragma unroll
        for (int ni = 0; ni < 8; ni++)
#pragma unroll
            for (int c = 0; c < 4; c++) acc[mi][ni][c] = 0.0f;

    // ---- prologue: generate stage 0 ----
    {
        const int j0 = 0;
        const uint32_t sB = s0 + SM_A_BYTES;
#pragma unroll
        for (int r = 0; r < 8; r++) {
            int idx = tid + r * 256;
            int n = idx >> 3, g = idx & 7;
            cp_async16(sB + swz((uint32_t)(n * 128 + g * 16)),
                       g_wt + (size_t)(v0 + n) * JJ + j0 + g * 8);
        }
        CP_COMMIT();
        float2 e2 = *(const float2*)(encrow + j0 + 2 * jp);
        float2 d2[8];
#pragma unroll
        for (int i = 0; i < 8; i++)
            d2[i] = *(const float2*)(decb + (size_t)(ug + i * 8) * JJ + j0 + 2 * jp);
#pragma unroll
        for (int i = 0; i < 8; i++) {
            int u = ug + i * 8;
            float x0 = tanh_approx(e2.x + d2[i].x);
            float x1 = tanh_approx(e2.y + d2[i].y);
            __half2 h2 = __floats2half2_rn(x0, x1);
            *(uint32_t*)(smem + swz((uint32_t)(u * 128 + jp * 4))) = *(uint32_t*)&h2;
        }
        CP_WAIT0();
        __syncthreads();
    }

    // ---- main pipeline ----
    for (int kc = 0; kc < NCHUNK; kc++) {
        const uint32_t cur = (uint32_t)(kc & 1) * STAGE_BYTES;
        const uint32_t nxt = (uint32_t)((kc + 1) & 1) * STAGE_BYTES;
        const bool has_next = (kc + 1) < NCHUNK;
        const int j0n = (kc + 1) * KC;

        // -- issue next-chunk loads first (in flight during MMA) --
        float2 e2, d2[8];
        if (has_next) {
            const uint32_t sBn = s0 + nxt + SM_A_BYTES;
#pragma unroll
            for (int r = 0; r < 8; r++) {
                int idx = tid + r * 256;
                int n = idx >> 3, g = idx & 7;
                cp_async16(sBn + swz((uint32_t)(n * 128 + g * 16)),
                           g_wt + (size_t)(v0 + n) * JJ + j0n + g * 8);
            }
            CP_COMMIT();
            e2 = *(const float2*)(encrow + j0n + 2 * jp);
#pragma unroll
            for (int i = 0; i < 8; i++)
                d2[i] = *(const float2*)(decb + (size_t)(ug + i * 8) * JJ + j0n + 2 * jp);
        }

        // -- MMA on current stage --
        const uint32_t sAc = s0 + cur;
        const uint32_t sBc = s0 + cur + SM_A_BYTES;
#pragma unroll
        for (int ks = 0; ks < 4; ks++) {
            const int k0b = ks * 32;
            uint32_t a[2][4];
#pragma unroll
            for (int mi = 0; mi < 2; mi++) {
                uint32_t addr = sAc +
                    swz((uint32_t)((a_row + mi * 16) * 128 + k0b + a_kb));
                ldsm_x4(addr, a[mi][0], a[mi][1], a[mi][2], a[mi][3]);
            }
            uint32_t bf[8][2];
#pragma unroll
            for (int nq = 0; nq < 4; nq++) {
                uint32_t addr = sBc +
                    swz((uint32_t)((b_nrow + nq * 16) * 128 + k0b + b_kb));
                ldsm_x4(addr, bf[nq * 2][0], bf[nq * 2][1],
                        bf[nq * 2 + 1][0], bf[nq * 2 + 1][1]);
            }
#pragma unroll
            for (int mi = 0; mi < 2; mi++)
#pragma unroll
                for (int ni = 0; ni < 8; ni++)
                    mma16816(acc[mi][ni], a[mi], bf[ni]);
        }

        // -- consume next-chunk loads: tanh -> STS (under tensor drain) --
        if (has_next) {
            char* sAn = smem + nxt;
#pragma unroll
            for (int i = 0; i < 8; i++) {
                int u = ug + i * 8;
                float x0 = tanh_approx(e2.x + d2[i].x);
                float x1 = tanh_approx(e2.y + d2[i].y);
                __half2 h2 = __floats2half2_rn(x0, x1);
                *(uint32_t*)(sAn + swz((uint32_t)(u * 128 + jp * 4))) = *(uint32_t*)&h2;
            }
            CP_WAIT0();
        }
        __syncthreads();
    }

    // ---- Epilogue: +bias, write fp32 ----
    {
        const int rowb = warp_m * 32 + (lane >> 2);
        const int colb = warp_n * 64 + (lane & 3) * 2;
        float* outbt = out + ((size_t)bt * UU + u0) * VV + v0;
        const float* bp = b_joint + v0;
#pragma unroll
        for (int ni = 0; ni < 8; ni++) {
            int c_ = colb + ni * 8;
            float2 b2 = *(const float2*)(bp + c_);
#pragma unroll
            for (int mi = 0; mi < 2; mi++) {
                int r_ = rowb + mi * 16;
                float2 o0 = { acc[mi][ni][0] + b2.x, acc[mi][ni][1] + b2.y };
                float2 o1 = { acc[mi][ni][2] + b2.x, acc[mi][ni][3] + b2.y };
                *(float2*)(outbt + (size_t)r_ * VV + c_) = o0;
                *(float2*)(outbt + (size_t)(r_ + 8) * VV + c_) = o1;
            }
        }
    }
}

// ============================================================================
// Launch
// ============================================================================
extern "C" void kernel_launch(void* const* d_in, const int* in_sizes, int n_in,
                              void* d_out, int out_size) {
    const float* enc     = (const float*)d_in[0];
    const float* dec     = (const float*)d_in[1];
    const float* W_enc   = (const float*)d_in[2];
    const float* b_enc   = (const float*)d_in[3];
    const float* W_dec   = (const float*)d_in[4];
    const float* b_dec   = (const float*)d_in[5];
    const float* W_joint = (const float*)d_in[6];
    const float* b_joint = (const float*)d_in[7];
    float* out = (float*)d_out;

    void *p_encp = nullptr, *p_decp = nullptr;
    cudaGetSymbolAddress(&p_encp, g_enc_proj);
    cudaGetSymbolAddress(&p_decp, g_dec_proj);

    // enc_proj: (1024, 512) x (512, 640)
    proj_gemm_kernel<<<dim3(JJ / 64, (BB * TT) / 64), 256>>>(
        enc, W_enc, b_enc, (float*)p_encp, BB * TT, JJ, EE);
    // dec_proj: (512, 640) x (640, 640)
    proj_gemm_kernel<<<dim3(JJ / 64, (BB * UU) / 64), 256>>>(
        dec, W_dec, b_dec, (float*)p_decp, BB * UU, JJ, DD);
    // W_joint transpose -> fp16
    transpose_fp16_kernel<<<dim3(VV / 32, JJ / 32), dim3(32, 8)>>>(W_joint);

    // fused joint + vocab GEMM
    cudaFuncSetAttribute(joint_vocab_kernel,
                         cudaFuncAttributeMaxDynamicSharedMemorySize, SM_TOTAL);
    joint_vocab_kernel<<<dim3(8, BB * TT), 256, SM_TOTAL>>>(b_joint, out);
}